// round 2
// baseline (speedup 1.0000x reference)
#include <cuda_runtime.h>

#define MAX_N 100000

// ---------------- scratch (static __device__ arrays, no allocation) -------
__device__ float g_h1  [MAX_N * 64];
__device__ float g_als1[MAX_N * 4];
__device__ float g_ald1[MAX_N * 4];
__device__ float g_den1[MAX_N * 4];
__device__ float g_out1[MAX_N * 64];
__device__ float g_h2  [MAX_N * 128];
__device__ float g_als2[MAX_N * 4];
__device__ float g_ald2[MAX_N * 4];
__device__ float g_den2[MAX_N * 4];
__device__ float g_out2[MAX_N * 128];

// ---------------- GEMM: C[M,NC] = (A[M,K] (+abias)) @ W[K,NC] -------------
// tile 128 rows x 64 cols, k-chunk 32, 256 threads, 8x4 microtile.
template<int K, int NC, bool ADD_BIAS>
__global__ __launch_bounds__(256)
void gemm_kernel(const float* __restrict__ A, const float* __restrict__ W,
                 const float* __restrict__ abias, float* __restrict__ C, int M)
{
    constexpr int KC = 32;
    __shared__ float As[128][KC + 4];   // pad 4: row stride 144B (16B aligned)
    __shared__ float Bs[KC][64];

    const int tx = threadIdx.x & 15;
    const int ty = threadIdx.x >> 4;
    const int row0 = blockIdx.x * 128;
    const int col0 = blockIdx.y * 64;

    float acc[8][4];
#pragma unroll
    for (int i = 0; i < 8; i++)
#pragma unroll
        for (int j = 0; j < 4; j++) acc[i][j] = 0.f;

    for (int kk = 0; kk < K; kk += KC) {
        // load A tile: 128 rows x 32 cols = 1024 float4
#pragma unroll
        for (int i = 0; i < 4; i++) {
            int idx = threadIdx.x + i * 256;
            int r = idx >> 3, c4 = idx & 7;
            float4 v = make_float4(0.f, 0.f, 0.f, 0.f);
            int gr = row0 + r;
            if (gr < M)
                v = *(const float4*)(A + (size_t)gr * K + kk + c4 * 4);
            if (ADD_BIAS) {
                v.x += abias[kk + c4 * 4 + 0];
                v.y += abias[kk + c4 * 4 + 1];
                v.z += abias[kk + c4 * 4 + 2];
                v.w += abias[kk + c4 * 4 + 3];
            }
            *(float4*)&As[r][c4 * 4] = v;
        }
        // load B tile: 32 rows x 64 cols = 512 float4
#pragma unroll
        for (int i = 0; i < 2; i++) {
            int idx = threadIdx.x + i * 256;
            int r = idx >> 4, c4 = idx & 15;
            *(float4*)&Bs[r][c4 * 4] =
                *(const float4*)(W + (size_t)(kk + r) * NC + col0 + c4 * 4);
        }
        __syncthreads();

#pragma unroll
        for (int k = 0; k < KC; k++) {
            float4 b = *(float4*)&Bs[k][tx * 4];
#pragma unroll
            for (int i = 0; i < 8; i++) {
                float a = As[ty * 8 + i][k];
                acc[i][0] += a * b.x;
                acc[i][1] += a * b.y;
                acc[i][2] += a * b.z;
                acc[i][3] += a * b.w;
            }
        }
        __syncthreads();
    }

#pragma unroll
    for (int i = 0; i < 8; i++) {
        int gr = row0 + ty * 8 + i;
        if (gr < M)
            *(float4*)(C + (size_t)gr * NC + col0 + tx * 4) =
                make_float4(acc[i][0], acc[i][1], acc[i][2], acc[i][3]);
    }
}

// ---------------- attention logits: als/ald[n,4] = h[n,h,:] . a[h,:] ------
template<int C>
__global__ void al_kernel(const float* __restrict__ h,
                          const float* __restrict__ a_src,
                          const float* __restrict__ a_dst,
                          float* __restrict__ als, float* __restrict__ ald, int n)
{
    int t = blockIdx.x * blockDim.x + threadIdx.x;
    if (t >= n * 4) return;
    int node = t >> 2, head = t & 3;
    const float* hp  = h + (size_t)node * (4 * C) + head * C;
    const float* asp = a_src + head * C;
    const float* adp = a_dst + head * C;
    float s1 = 0.f, s2 = 0.f;
#pragma unroll
    for (int c = 0; c < C; c += 4) {
        float4 hv = *(const float4*)(hp + c);
        float4 av = *(const float4*)(asp + c);
        float4 dv = *(const float4*)(adp + c);
        s1 += hv.x * av.x + hv.y * av.y + hv.z * av.z + hv.w * av.w;
        s2 += hv.x * dv.x + hv.y * dv.y + hv.z * dv.z + hv.w * dv.w;
    }
    als[t] = s1;
    ald[t] = s2;
}

// ---------------- softmax denominator (self-loops appended implicitly) ----
__global__ void denom_kernel(const int* __restrict__ se,
                             const int* __restrict__ de,
                             int E, int n,
                             const float* __restrict__ als,
                             const float* __restrict__ ald,
                             float* __restrict__ den)
{
    int t = blockIdx.x * blockDim.x + threadIdx.x;
    int total = E + n;
    if (t >= total) return;
    int s, d;
    if (t < E) { s = se[t]; d = de[t]; }
    else       { s = t - E; d = s; }
    float4 a = *(const float4*)(als + (size_t)s * 4);
    float4 b = *(const float4*)(ald + (size_t)d * 4);
    float e0 = a.x + b.x, e1 = a.y + b.y, e2 = a.z + b.z, e3 = a.w + b.w;
    e0 = e0 > 0.f ? e0 : 0.2f * e0;
    e1 = e1 > 0.f ? e1 : 0.2f * e1;
    e2 = e2 > 0.f ? e2 : 0.2f * e2;
    e3 = e3 > 0.f ? e3 : 0.2f * e3;
    atomicAdd(&den[(size_t)d * 4 + 0], __expf(e0));
    atomicAdd(&den[(size_t)d * 4 + 1], __expf(e1));
    atomicAdd(&den[(size_t)d * 4 + 2], __expf(e2));
    atomicAdd(&den[(size_t)d * 4 + 3], __expf(e3));
}

// ---------------- weighted aggregation: warp per edge ---------------------
template<int C>
__global__ void agg_kernel(const int* __restrict__ se,
                           const int* __restrict__ de,
                           int E, int n,
                           const float* __restrict__ als,
                           const float* __restrict__ ald,
                           const float* __restrict__ den,
                           const float* __restrict__ h,
                           float* __restrict__ out)
{
    constexpr int HC = 4 * C;
    constexpr int ELEMS = HC / 32;
    int gw = (blockIdx.x * blockDim.x + threadIdx.x) >> 5;
    int lane = threadIdx.x & 31;
    int total = E + n;
    if (gw >= total) return;
    int s, d;
    if (gw < E) { s = se[gw]; d = de[gw]; }
    else        { s = gw - E; d = s; }
    const float* hs = h + (size_t)s * HC;
    float* od = out + (size_t)d * HC;
#pragma unroll
    for (int k = 0; k < ELEMS; k++) {
        int i = lane + 32 * k;
        int head = i / C;
        float e = als[(size_t)s * 4 + head] + ald[(size_t)d * 4 + head];
        e = e > 0.f ? e : 0.2f * e;
        float w = __expf(e) / den[(size_t)d * 4 + head];
        atomicAdd(od + i, w * __ldg(hs + i));
    }
}

// ---------------- head-mean + bias + elu + log_softmax --------------------
__global__ void final_kernel(const float* __restrict__ out2,
                             const float* __restrict__ b2,
                             float* __restrict__ y, int n)
{
    int gw = (blockIdx.x * blockDim.x + threadIdx.x) >> 5;
    int lane = threadIdx.x & 31;
    if (gw >= n) return;
    const float* p = out2 + (size_t)gw * 128;
    float v = 0.25f * (p[lane] + p[lane + 32] + p[lane + 64] + p[lane + 96])
            + b2[lane];
    v = v > 0.f ? v : expm1f(v);          // elu
    float m = v;
#pragma unroll
    for (int o = 16; o > 0; o >>= 1)
        m = fmaxf(m, __shfl_xor_sync(0xffffffffu, m, o));
    float ex = expf(v - m);
    float ssum = ex;
#pragma unroll
    for (int o = 16; o > 0; o >>= 1)
        ssum += __shfl_xor_sync(0xffffffffu, ssum, o);
    y[(size_t)gw * 32 + lane] = v - m - logf(ssum);
}

// ---------------------------------------------------------------------------
extern "C" void kernel_launch(void* const* d_in, const int* in_sizes, int n_in,
                              void* d_out, int out_size)
{
    const float* x   = (const float*)d_in[0];
    const int*   ei  = (const int*)d_in[1];     // int32! (JAX default, no x64)
    const float* W1  = (const float*)d_in[2];
    const float* as1 = (const float*)d_in[3];
    const float* ad1 = (const float*)d_in[4];
    const float* b1  = (const float*)d_in[5];
    const float* W2  = (const float*)d_in[6];
    const float* as2 = (const float*)d_in[7];
    const float* ad2 = (const float*)d_in[8];
    const float* b2  = (const float*)d_in[9];
    float*       y   = (float*)d_out;

    const int n = in_sizes[0] / 128;
    const int E = in_sizes[1] / 2;
    const int* se = ei;
    const int* de = ei + E;
    const int total = E + n;

    float *h1, *als1, *ald1, *den1, *out1, *h2, *als2, *ald2, *den2, *out2;
    cudaGetSymbolAddress((void**)&h1,   g_h1);
    cudaGetSymbolAddress((void**)&als1, g_als1);
    cudaGetSymbolAddress((void**)&ald1, g_ald1);
    cudaGetSymbolAddress((void**)&den1, g_den1);
    cudaGetSymbolAddress((void**)&out1, g_out1);
    cudaGetSymbolAddress((void**)&h2,   g_h2);
    cudaGetSymbolAddress((void**)&als2, g_als2);
    cudaGetSymbolAddress((void**)&ald2, g_ald2);
    cudaGetSymbolAddress((void**)&den2, g_den2);
    cudaGetSymbolAddress((void**)&out2, g_out2);

    // zero accumulators (memset nodes are graph-capturable)
    cudaMemsetAsync(den1, 0, (size_t)n * 4 * sizeof(float));
    cudaMemsetAsync(out1, 0, (size_t)n * 64 * sizeof(float));
    cudaMemsetAsync(den2, 0, (size_t)n * 4 * sizeof(float));
    cudaMemsetAsync(out2, 0, (size_t)n * 128 * sizeof(float));

    // -------- layer 1 --------
    gemm_kernel<128, 64, false>
        <<<dim3((n + 127) / 128, 1), 256>>>(x, W1, nullptr, h1, n);
    al_kernel<16><<<(n * 4 + 255) / 256, 256>>>(h1, as1, ad1, als1, ald1, n);
    denom_kernel<<<(total + 255) / 256, 256>>>(se, de, E, n, als1, ald1, den1);
    agg_kernel<16><<<(int)(((long long)total * 32 + 255) / 256), 256>>>(
        se, de, E, n, als1, ald1, den1, h1, out1);

    // -------- layer 2 --------
    gemm_kernel<64, 128, true>
        <<<dim3((n + 127) / 128, 2), 256>>>(out1, W2, b1, h2, n);
    al_kernel<32><<<(n * 4 + 255) / 256, 256>>>(h2, as2, ad2, als2, ald2, n);
    denom_kernel<<<(total + 255) / 256, 256>>>(se, de, E, n, als2, ald2, den2);
    agg_kernel<32><<<(int)(((long long)total * 32 + 255) / 256), 256>>>(
        se, de, E, n, als2, ald2, den2, h2, out2);

    // -------- epilogue --------
    final_kernel<<<(n * 32 + 255) / 256, 256>>>(out2, b2, y, n);
}

// round 3
// speedup vs baseline: 3.0299x; 3.0299x over previous
#include <cuda_runtime.h>

#define MAX_N 100000
#define MAX_E 1600000

// ---------------- scratch (static __device__ arrays) ----------------------
__device__ float g_h1  [MAX_N * 64];
__device__ float g_als1[MAX_N * 4];
__device__ float g_ald1[MAX_N * 4];
__device__ float g_out1[MAX_N * 64];
__device__ float g_h2  [MAX_N * 128];
__device__ float g_als2[MAX_N * 4];
__device__ float g_ald2[MAX_N * 4];
__device__ int   g_rowptr[MAX_N + 1];
__device__ int   g_cursor[MAX_N];
__device__ int   g_bsum[128];
__device__ int   g_ssrc[MAX_E];

// ---------------- GEMM: C[M,NC] = A[M,K] @ W[K,NC] ------------------------
template<int K, int NC>
__global__ __launch_bounds__(256)
void gemm_kernel(const float* __restrict__ A, const float* __restrict__ W,
                 float* __restrict__ C, int M)
{
    constexpr int KC = 32;
    __shared__ float As[128][KC + 4];
    __shared__ float Bs[KC][64];

    const int tx = threadIdx.x & 15;
    const int ty = threadIdx.x >> 4;
    const int row0 = blockIdx.x * 128;
    const int col0 = blockIdx.y * 64;

    float acc[8][4];
#pragma unroll
    for (int i = 0; i < 8; i++)
#pragma unroll
        for (int j = 0; j < 4; j++) acc[i][j] = 0.f;

    for (int kk = 0; kk < K; kk += KC) {
#pragma unroll
        for (int i = 0; i < 4; i++) {
            int idx = threadIdx.x + i * 256;
            int r = idx >> 3, c4 = idx & 7;
            float4 v = make_float4(0.f, 0.f, 0.f, 0.f);
            int gr = row0 + r;
            if (gr < M)
                v = *(const float4*)(A + (size_t)gr * K + kk + c4 * 4);
            *(float4*)&As[r][c4 * 4] = v;
        }
#pragma unroll
        for (int i = 0; i < 2; i++) {
            int idx = threadIdx.x + i * 256;
            int r = idx >> 4, c4 = idx & 15;
            *(float4*)&Bs[r][c4 * 4] =
                *(const float4*)(W + (size_t)(kk + r) * NC + col0 + c4 * 4);
        }
        __syncthreads();

#pragma unroll
        for (int k = 0; k < KC; k++) {
            float4 b = *(float4*)&Bs[k][tx * 4];
#pragma unroll
            for (int i = 0; i < 8; i++) {
                float a = As[ty * 8 + i][k];
                acc[i][0] += a * b.x;
                acc[i][1] += a * b.y;
                acc[i][2] += a * b.z;
                acc[i][3] += a * b.w;
            }
        }
        __syncthreads();
    }

#pragma unroll
    for (int i = 0; i < 8; i++) {
        int gr = row0 + ty * 8 + i;
        if (gr < M)
            *(float4*)(C + (size_t)gr * NC + col0 + tx * 4) =
                make_float4(acc[i][0], acc[i][1], acc[i][2], acc[i][3]);
    }
}

// ---------------- attention logits ----------------------------------------
template<int C>
__global__ void al_kernel(const float* __restrict__ h,
                          const float* __restrict__ a_src,
                          const float* __restrict__ a_dst,
                          float* __restrict__ als, float* __restrict__ ald, int n)
{
    int t = blockIdx.x * blockDim.x + threadIdx.x;
    if (t >= n * 4) return;
    int node = t >> 2, head = t & 3;
    const float* hp  = h + (size_t)node * (4 * C) + head * C;
    const float* asp = a_src + head * C;
    const float* adp = a_dst + head * C;
    float s1 = 0.f, s2 = 0.f;
#pragma unroll
    for (int c = 0; c < C; c += 4) {
        float4 hv = *(const float4*)(hp + c);
        float4 av = *(const float4*)(asp + c);
        float4 dv = *(const float4*)(adp + c);
        s1 += hv.x * av.x + hv.y * av.y + hv.z * av.z + hv.w * av.w;
        s2 += hv.x * dv.x + hv.y * dv.y + hv.z * dv.z + hv.w * dv.w;
    }
    als[t] = s1;
    ald[t] = s2;
}

// ---------------- CSR build ------------------------------------------------
__global__ void hist_kernel(const int* __restrict__ de, int E, int* __restrict__ cnt)
{
    int e = blockIdx.x * blockDim.x + threadIdx.x;
    if (e < E) atomicAdd(&cnt[de[e]], 1);
}

// exclusive scan, 2048-element chunks (256 threads x 8)
__global__ void scan_k1(int* __restrict__ data, int n, int* __restrict__ bsum)
{
    __shared__ int sh[256];
    int base = blockIdx.x * 2048 + threadIdx.x * 8;
    int v[8];
    int run = 0;
#pragma unroll
    for (int k = 0; k < 8; k++) {
        int t = (base + k < n) ? data[base + k] : 0;
        v[k] = run;
        run += t;
    }
    sh[threadIdx.x] = run;
    __syncthreads();
    for (int off = 1; off < 256; off <<= 1) {
        int t = (threadIdx.x >= off) ? sh[threadIdx.x - off] : 0;
        __syncthreads();
        sh[threadIdx.x] += t;
        __syncthreads();
    }
    int excl = sh[threadIdx.x] - run;
#pragma unroll
    for (int k = 0; k < 8; k++)
        if (base + k < n) data[base + k] = v[k] + excl;
    if (threadIdx.x == 255) bsum[blockIdx.x] = sh[255];
}

__global__ void scan_k2(int* __restrict__ bsum, int nb)
{
    if (threadIdx.x == 0) {
        int run = 0;
        for (int i = 0; i < nb; i++) { int t = bsum[i]; bsum[i] = run; run += t; }
    }
}

__global__ void scan_k3(int* __restrict__ data, int n, const int* __restrict__ bsum,
                        int* __restrict__ cursor, int E)
{
    int i = blockIdx.x * blockDim.x + threadIdx.x;
    if (i < n) {
        int v = data[i] + bsum[i >> 11];
        data[i] = v;
        cursor[i] = v;
    }
    if (i == 0) data[n] = E;
}

__global__ void scatter_kernel(const int* __restrict__ se, const int* __restrict__ de,
                               int E, int* __restrict__ cursor, int* __restrict__ ssrc)
{
    int e = blockIdx.x * blockDim.x + threadIdx.x;
    if (e < E) {
        int pos = atomicAdd(&cursor[de[e]], 1);
        ssrc[pos] = se[e];
    }
}

// ---------------- fused softmax-aggregate, CSR (layer 1) -------------------
// C=16: half-warp (16 lanes) per dst node; fused denominator; adds bias.
template<int C>
__global__ void agg_csr_kernel(const int* __restrict__ rowptr,
                               const int* __restrict__ ssrc,
                               const float* __restrict__ als,
                               const float* __restrict__ ald,
                               const float* __restrict__ h,
                               const float* __restrict__ bias,
                               float* __restrict__ out, int n)
{
    constexpr int HC = 4 * C;
    constexpr int G  = HC / 4;                 // lanes per node
    int gt   = blockIdx.x * blockDim.x + threadIdx.x;
    int node = gt / G;
    int li   = gt % G;
    if (node >= n) return;
    int head = li / (C / 4);

    float aldv = ald[(size_t)node * 4 + head];

    // self-loop term
    float e0 = als[(size_t)node * 4 + head] + aldv;
    e0 = e0 > 0.f ? e0 : 0.2f * e0;
    float ex = __expf(e0);
    float den = ex;
    float4 hv = ((const float4*)(h + (size_t)node * HC))[li];
    float4 acc = make_float4(ex * hv.x, ex * hv.y, ex * hv.z, ex * hv.w);

    int j1 = rowptr[node + 1];
    for (int j = rowptr[node]; j < j1; j++) {
        int s = ssrc[j];
        float e = als[(size_t)s * 4 + head] + aldv;
        e = e > 0.f ? e : 0.2f * e;
        float w = __expf(e);
        den += w;
        float4 v = ((const float4*)(h + (size_t)s * HC))[li];
        acc.x = fmaf(w, v.x, acc.x);
        acc.y = fmaf(w, v.y, acc.y);
        acc.z = fmaf(w, v.z, acc.z);
        acc.w = fmaf(w, v.w, acc.w);
    }
    float inv = 1.f / den;
    float4 o;
    o.x = acc.x * inv + bias[li * 4 + 0];
    o.y = acc.y * inv + bias[li * 4 + 1];
    o.z = acc.z * inv + bias[li * 4 + 2];
    o.w = acc.w * inv + bias[li * 4 + 3];
    ((float4*)(out + (size_t)node * HC))[li] = o;
}

// ---------------- layer 2: aggregate + head-mean + bias + elu + logsoftmax -
// C=32 (HC=128): warp per node, fully fused epilogue.
__global__ void agg2_final_kernel(const int* __restrict__ rowptr,
                                  const int* __restrict__ ssrc,
                                  const float* __restrict__ als,
                                  const float* __restrict__ ald,
                                  const float* __restrict__ h,
                                  const float* __restrict__ b2,
                                  float* __restrict__ y, int n)
{
    int lane = threadIdx.x & 31;
    int node = (blockIdx.x * blockDim.x + threadIdx.x) >> 5;
    if (node >= n) return;
    int head = lane >> 3;

    float aldv = ald[(size_t)node * 4 + head];

    float e0 = als[(size_t)node * 4 + head] + aldv;
    e0 = e0 > 0.f ? e0 : 0.2f * e0;
    float ex = __expf(e0);
    float den = ex;
    float4 hv = ((const float4*)(h + (size_t)node * 128))[lane];
    float4 acc = make_float4(ex * hv.x, ex * hv.y, ex * hv.z, ex * hv.w);

    int j1 = rowptr[node + 1];
    for (int j = rowptr[node]; j < j1; j++) {
        int s = ssrc[j];
        float e = als[(size_t)s * 4 + head] + aldv;
        e = e > 0.f ? e : 0.2f * e;
        float w = __expf(e);
        den += w;
        float4 v = ((const float4*)(h + (size_t)s * 128))[lane];
        acc.x = fmaf(w, v.x, acc.x);
        acc.y = fmaf(w, v.y, acc.y);
        acc.z = fmaf(w, v.z, acc.z);
        acc.w = fmaf(w, v.w, acc.w);
    }
    float inv = 1.f / den;
    float4 v = make_float4(acc.x * inv, acc.y * inv, acc.z * inv, acc.w * inv);

    // mean over 4 heads: lanes {l, l^8, l^16, l^24} hold the same channels
    v.x += __shfl_xor_sync(0xffffffffu, v.x, 8);
    v.y += __shfl_xor_sync(0xffffffffu, v.y, 8);
    v.z += __shfl_xor_sync(0xffffffffu, v.z, 8);
    v.w += __shfl_xor_sync(0xffffffffu, v.w, 8);
    v.x += __shfl_xor_sync(0xffffffffu, v.x, 16);
    v.y += __shfl_xor_sync(0xffffffffu, v.y, 16);
    v.z += __shfl_xor_sync(0xffffffffu, v.z, 16);
    v.w += __shfl_xor_sync(0xffffffffu, v.w, 16);
    int c0 = (lane & 7) * 4;
    v.x = 0.25f * v.x + b2[c0 + 0];
    v.y = 0.25f * v.y + b2[c0 + 1];
    v.z = 0.25f * v.z + b2[c0 + 2];
    v.w = 0.25f * v.w + b2[c0 + 3];
    // elu
    v.x = v.x > 0.f ? v.x : expm1f(v.x);
    v.y = v.y > 0.f ? v.y : expm1f(v.y);
    v.z = v.z > 0.f ? v.z : expm1f(v.z);
    v.w = v.w > 0.f ? v.w : expm1f(v.w);
    // log_softmax over 32 channels spread across 8-lane groups
    float m = fmaxf(fmaxf(v.x, v.y), fmaxf(v.z, v.w));
#pragma unroll
    for (int off = 1; off < 8; off <<= 1)
        m = fmaxf(m, __shfl_xor_sync(0xffffffffu, m, off));
    float s = expf(v.x - m) + expf(v.y - m) + expf(v.z - m) + expf(v.w - m);
#pragma unroll
    for (int off = 1; off < 8; off <<= 1)
        s += __shfl_xor_sync(0xffffffffu, s, off);
    float ls = m + logf(s);
    if (lane < 8) {
        float4 o = make_float4(v.x - ls, v.y - ls, v.z - ls, v.w - ls);
        ((float4*)(y + (size_t)node * 32))[lane] = o;
    }
}

// ---------------------------------------------------------------------------
extern "C" void kernel_launch(void* const* d_in, const int* in_sizes, int n_in,
                              void* d_out, int out_size)
{
    const float* x   = (const float*)d_in[0];
    const int*   ei  = (const int*)d_in[1];
    const float* W1  = (const float*)d_in[2];
    const float* as1 = (const float*)d_in[3];
    const float* ad1 = (const float*)d_in[4];
    const float* b1  = (const float*)d_in[5];
    const float* W2  = (const float*)d_in[6];
    const float* as2 = (const float*)d_in[7];
    const float* ad2 = (const float*)d_in[8];
    const float* b2  = (const float*)d_in[9];
    float*       y   = (float*)d_out;

    const int n = in_sizes[0] / 128;
    const int E = in_sizes[1] / 2;
    const int* se = ei;
    const int* de = ei + E;

    float *h1, *als1, *ald1, *out1, *h2, *als2, *ald2;
    int *rowptr, *cursor, *bsum, *ssrc;
    cudaGetSymbolAddress((void**)&h1,     g_h1);
    cudaGetSymbolAddress((void**)&als1,   g_als1);
    cudaGetSymbolAddress((void**)&ald1,   g_ald1);
    cudaGetSymbolAddress((void**)&out1,   g_out1);
    cudaGetSymbolAddress((void**)&h2,     g_h2);
    cudaGetSymbolAddress((void**)&als2,   g_als2);
    cudaGetSymbolAddress((void**)&ald2,   g_ald2);
    cudaGetSymbolAddress((void**)&rowptr, g_rowptr);
    cudaGetSymbolAddress((void**)&cursor, g_cursor);
    cudaGetSymbolAddress((void**)&bsum,   g_bsum);
    cudaGetSymbolAddress((void**)&ssrc,   g_ssrc);

    const int nb = (n + 2047) / 2048;

    // ---- CSR build (shared by both layers) ----
    cudaMemsetAsync(rowptr, 0, (size_t)n * sizeof(int));
    hist_kernel<<<(E + 255) / 256, 256>>>(de, E, rowptr);
    scan_k1<<<nb, 256>>>(rowptr, n, bsum);
    scan_k2<<<1, 32>>>(bsum, nb);
    scan_k3<<<(n + 255) / 256, 256>>>(rowptr, n, bsum, cursor, E);
    scatter_kernel<<<(E + 255) / 256, 256>>>(se, de, E, cursor, ssrc);

    // ---- layer 1 ----
    gemm_kernel<128, 64>
        <<<dim3((n + 127) / 128, 1), 256>>>(x, W1, h1, n);
    al_kernel<16><<<(n * 4 + 255) / 256, 256>>>(h1, as1, ad1, als1, ald1, n);
    agg_csr_kernel<16><<<(int)(((long long)n * 16 + 255) / 256), 256>>>(
        rowptr, ssrc, als1, ald1, h1, b1, out1, n);

    // ---- layer 2 ----
    gemm_kernel<64, 128>
        <<<dim3((n + 127) / 128, 2), 256>>>(out1, W2, h2, n);
    al_kernel<32><<<(n * 4 + 255) / 256, 256>>>(h2, as2, ad2, als2, ald2, n);
    agg2_final_kernel<<<(int)(((long long)n * 32 + 255) / 256), 256>>>(
        rowptr, ssrc, als2, ald2, h2, b2, y, n);
}